// round 5
// baseline (speedup 1.0000x reference)
#include <cuda_runtime.h>

// GRU-ODE: B=32768 rows, T=28, DIM=H=32, 10-step RK4, RHS = 2-layer tanh MLP.
// 8 threads per row (j-slice of 4), R=2 rows per thread, f32x2-packed FMAs.
// Per k-iter/thread: 1 LDS.128 (full 128B weight row per oct, conflict-free
// broadcast) + 2 SHFL(width 8) + 2 splat MOV + 4 FFMA2 => 16 FMA-ops.
// Live state ~90 regs: no spills (R4 lesson), 4-5 blocks/SM.

#define TT 28
#define NSTEPS 10
typedef unsigned long long u64;

struct __align__(16) SW {
    float T1[1024], T2[1024];       // T[k*32+j] = W[j*32+k] (transposed)
    float Tih[3][1024], Thh[3][1024];
    float b1[32], b2[32];
    float br[32], bz[32], bni[32], bnh[32];  // GRU biases (r,z presummed)
};

__device__ __forceinline__ u64 splat2(float x) {
    u64 d; asm("mov.b64 %0, {%1, %1};" : "=l"(d) : "f"(x)); return d;
}
__device__ __forceinline__ float2 unpack2(u64 v) {
    float2 r; asm("mov.b64 {%0, %1}, %2;" : "=f"(r.x), "=f"(r.y) : "l"(v)); return r;
}
__device__ __forceinline__ u64 fma2(u64 a, u64 b, u64 c) {
    u64 d; asm("fma.rn.f32x2 %0, %1, %2, %3;" : "=l"(d) : "l"(a), "l"(b), "l"(c)); return d;
}

__device__ __forceinline__ float sigmoidf_fast(float x) {
    return __fdividef(1.0f, 1.0f + __expf(-x));
}
__device__ __forceinline__ float tanhf_fast(float x) {
    return 1.0f - __fdividef(2.0f, 1.0f + __expf(2.0f * x));
}

// acc[r][p] (f32x2 over j=(ooff+2p, ooff+2p+1)) += y[r][k] * T[k*32+ooff+..].
// y distributed 4/thread across the 8-lane oct; k = src*4 + m.
template <int R>
__device__ __forceinline__ void mv8(const float* __restrict__ T, int ooff,
                                    const float (&y)[R][4], u64 (&a)[R][2]) {
#pragma unroll
    for (int src = 0; src < 8; ++src) {
#pragma unroll
        for (int m = 0; m < 4; ++m) {
            const int k = src * 4 + m;
            const ulonglong2 w = *reinterpret_cast<const ulonglong2*>(T + k * 32 + ooff);
#pragma unroll
            for (int r = 0; r < R; ++r) {
                const u64 s = splat2(__shfl_sync(0xffffffffu, y[r][m], src, 8));
                a[r][0] = fma2(s, w.x, a[r][0]);
                a[r][1] = fma2(s, w.y, a[r][1]);
            }
        }
    }
}

// f = tanh(y @ W1^T + b1) @ W2^T + b2 for 2 rows (this thread's 4-j slice).
__device__ __forceinline__ void rhs2(const SW* __restrict__ s, int ooff,
                                     const float (&y)[2][4], float (&f)[2][4]) {
    u64 acc[2][2];
#pragma unroll
    for (int p = 0; p < 2; ++p) {
        const u64 b = *reinterpret_cast<const u64*>(s->b1 + ooff + 2 * p);
        acc[0][p] = b; acc[1][p] = b;
    }
    mv8<2>(s->T1, ooff, y, acc);
    float z[2][4];
#pragma unroll
    for (int r = 0; r < 2; ++r)
#pragma unroll
        for (int p = 0; p < 2; ++p) {
            const float2 v = unpack2(acc[r][p]);
            z[r][2 * p]     = tanhf_fast(v.x);
            z[r][2 * p + 1] = tanhf_fast(v.y);
        }
#pragma unroll
    for (int p = 0; p < 2; ++p) {
        const u64 b = *reinterpret_cast<const u64*>(s->b2 + ooff + 2 * p);
        acc[0][p] = b; acc[1][p] = b;
    }
    mv8<2>(s->T2, ooff, z, acc);
#pragma unroll
    for (int r = 0; r < 2; ++r)
#pragma unroll
        for (int p = 0; p < 2; ++p) {
            const float2 v = unpack2(acc[r][p]);
            f[r][2 * p] = v.x; f[r][2 * p + 1] = v.y;
        }
}

__device__ __forceinline__ void rk4(const SW* __restrict__ s, int ooff,
                                    float (&h)[2][4], float span) {
    const float dt = span * (1.0f / NSTEPS);
#pragma unroll 1
    for (int st = 0; st < NSTEPS; ++st) {
        float yt[2][4], ks[2][4], kc[2][4];
#pragma unroll
        for (int r = 0; r < 2; ++r)
#pragma unroll
            for (int j = 0; j < 4; ++j) { yt[r][j] = h[r][j]; ks[r][j] = 0.0f; }
#pragma unroll 1
        for (int sg = 0; sg < 4; ++sg) {
            rhs2(s, ooff, yt, kc);
            const float ws = (sg == 1 || sg == 2) ? 2.0f : 1.0f;
            const float cn = (sg < 2) ? 0.5f * dt : dt;
#pragma unroll
            for (int r = 0; r < 2; ++r)
#pragma unroll
                for (int j = 0; j < 4; ++j) {
                    ks[r][j] = fmaf(ws, kc[r][j], ks[r][j]);
                    yt[r][j] = fmaf(cn, kc[r][j], h[r][j]);  // extra at sg=3: harmless
                }
        }
#pragma unroll
        for (int r = 0; r < 2; ++r)
#pragma unroll
            for (int j = 0; j < 4; ++j)
                h[r][j] = fmaf(dt * (1.0f / 6.0f), ks[r][j], h[r][j]);
    }
}

// PyTorch-order GRU (r,z,n) on 2 rows, 4-j slice.
__device__ __forceinline__ void gru2(const SW* __restrict__ s, int ooff,
                                     float (&h)[2][4], const float (&x)[2][4]) {
    u64 a1[2][2], a2[2][2];
    float rg[2][4], zg[2][4];
    // r gate
#pragma unroll
    for (int p = 0; p < 2; ++p) {
        const u64 b = *reinterpret_cast<const u64*>(s->br + ooff + 2 * p);
        a1[0][p] = b; a1[1][p] = b;
    }
    mv8<2>(s->Tih[0], ooff, x, a1);
    mv8<2>(s->Thh[0], ooff, h, a1);
#pragma unroll
    for (int r = 0; r < 2; ++r)
#pragma unroll
        for (int p = 0; p < 2; ++p) {
            const float2 v = unpack2(a1[r][p]);
            rg[r][2 * p]     = sigmoidf_fast(v.x);
            rg[r][2 * p + 1] = sigmoidf_fast(v.y);
        }
    // z gate
#pragma unroll
    for (int p = 0; p < 2; ++p) {
        const u64 b = *reinterpret_cast<const u64*>(s->bz + ooff + 2 * p);
        a1[0][p] = b; a1[1][p] = b;
    }
    mv8<2>(s->Tih[1], ooff, x, a1);
    mv8<2>(s->Thh[1], ooff, h, a1);
#pragma unroll
    for (int r = 0; r < 2; ++r)
#pragma unroll
        for (int p = 0; p < 2; ++p) {
            const float2 v = unpack2(a1[r][p]);
            zg[r][2 * p]     = sigmoidf_fast(v.x);
            zg[r][2 * p + 1] = sigmoidf_fast(v.y);
        }
    // n gate: input part and hidden part separately (r multiplies hidden part)
#pragma unroll
    for (int p = 0; p < 2; ++p) {
        const u64 bi = *reinterpret_cast<const u64*>(s->bni + ooff + 2 * p);
        const u64 bh = *reinterpret_cast<const u64*>(s->bnh + ooff + 2 * p);
        a1[0][p] = bi; a1[1][p] = bi;
        a2[0][p] = bh; a2[1][p] = bh;
    }
    mv8<2>(s->Tih[2], ooff, x, a1);
    mv8<2>(s->Thh[2], ooff, h, a2);
#pragma unroll
    for (int r = 0; r < 2; ++r)
#pragma unroll
        for (int p = 0; p < 2; ++p) {
            const float2 gi = unpack2(a1[r][p]);
            const float2 gh = unpack2(a2[r][p]);
            const float n0 = tanhf_fast(gi.x + rg[r][2 * p] * gh.x);
            const float n1 = tanhf_fast(gi.y + rg[r][2 * p + 1] * gh.y);
            h[r][2 * p]     = n0 + zg[r][2 * p]     * (h[r][2 * p]     - n0);
            h[r][2 * p + 1] = n1 + zg[r][2 * p + 1] * (h[r][2 * p + 1] - n1);
        }
}

__device__ __forceinline__ void load4(const float* __restrict__ p, float (&v)[4]) {
    const float4 a = *reinterpret_cast<const float4*>(p);
    v[0] = a.x; v[1] = a.y; v[2] = a.z; v[3] = a.w;
}

extern "C" __global__ void __launch_bounds__(128)
ode_gru_kernel(const float* __restrict__ inputs, const float* __restrict__ h0,
               const float* __restrict__ Wih, const float* __restrict__ Whh,
               const float* __restrict__ bih, const float* __restrict__ bhh,
               const float* __restrict__ W1, const float* __restrict__ b1,
               const float* __restrict__ W2, const float* __restrict__ b2,
               float* __restrict__ out, int B) {
    __shared__ SW s;
    for (int i = threadIdx.x; i < 1024; i += blockDim.x) {
        const int j = i >> 5, k = i & 31;
        s.T1[k * 32 + j] = W1[i];
        s.T2[k * 32 + j] = W2[i];
    }
    for (int i = threadIdx.x; i < 3072; i += blockDim.x) {
        const int g = i >> 10, r = (i >> 5) & 31, k = i & 31;
        s.Tih[g][k * 32 + r] = Wih[i];
        s.Thh[g][k * 32 + r] = Whh[i];
    }
    for (int i = threadIdx.x; i < 32; i += blockDim.x) {
        s.b1[i]  = b1[i];            s.b2[i]  = b2[i];
        s.br[i]  = bih[i] + bhh[i];  s.bz[i]  = bih[32 + i] + bhh[32 + i];
        s.bni[i] = bih[64 + i];      s.bnh[i] = bhh[64 + i];
    }
    __syncthreads();

    const int gt   = blockIdx.x * blockDim.x + threadIdx.x;
    const int oct  = gt >> 3;             // row-pair group (8 lanes each)
    const int ooff = (gt & 7) * 4;        // j-slice offset
    const int rowA = oct * 2;
    const int rowB = rowA + 1;
    if (rowB >= B) return;                // B even: uniform per warp

    float h[2][4];
    load4(h0 + (size_t)rowA * 32 + ooff, h[0]);
    load4(h0 + (size_t)rowB * 32 + ooff, h[1]);

    const float* xa = inputs + (size_t)rowA * TT * 32 + ooff;
    const float* xb = inputs + (size_t)rowB * TT * 32 + ooff;

    // initial integration over [0, 1]
    rk4(&s, ooff, h, 1.0f);

#pragma unroll 1
    for (int t = 0; t < TT; ++t) {
        float x[2][4];
        load4(xa + t * 32, x[0]);
        load4(xb + t * 32, x[1]);
        gru2(&s, ooff, h, x);
        if (t < TT - 1) rk4(&s, ooff, h, 1.0f);
    }

    // h_start -> out[0], then 14-unit integration -> out[1]
    {
        float4 oa, ob;
        oa.x = fmaxf(h[0][0], 0.0f); oa.y = fmaxf(h[0][1], 0.0f);
        oa.z = fmaxf(h[0][2], 0.0f); oa.w = fmaxf(h[0][3], 0.0f);
        ob.x = fmaxf(h[1][0], 0.0f); ob.y = fmaxf(h[1][1], 0.0f);
        ob.z = fmaxf(h[1][2], 0.0f); ob.w = fmaxf(h[1][3], 0.0f);
        *reinterpret_cast<float4*>(out + (size_t)rowA * 32 + ooff) = oa;
        *reinterpret_cast<float4*>(out + (size_t)rowB * 32 + ooff) = ob;
    }
    rk4(&s, ooff, h, 14.0f);
    {
        float4 oa, ob;
        oa.x = fmaxf(h[0][0], 0.0f); oa.y = fmaxf(h[0][1], 0.0f);
        oa.z = fmaxf(h[0][2], 0.0f); oa.w = fmaxf(h[0][3], 0.0f);
        ob.x = fmaxf(h[1][0], 0.0f); ob.y = fmaxf(h[1][1], 0.0f);
        ob.z = fmaxf(h[1][2], 0.0f); ob.w = fmaxf(h[1][3], 0.0f);
        *reinterpret_cast<float4*>(out + (size_t)B * 32 + (size_t)rowA * 32 + ooff) = oa;
        *reinterpret_cast<float4*>(out + (size_t)B * 32 + (size_t)rowB * 32 + ooff) = ob;
    }
}

extern "C" void kernel_launch(void* const* d_in, const int* in_sizes, int n_in,
                              void* d_out, int out_size) {
    const float* inputs = (const float*)d_in[0];
    const float* h0     = (const float*)d_in[1];
    const float* Wih    = (const float*)d_in[2];
    const float* Whh    = (const float*)d_in[3];
    const float* bih    = (const float*)d_in[4];
    const float* bhh    = (const float*)d_in[5];
    const float* W1     = (const float*)d_in[6];
    const float* b1     = (const float*)d_in[7];
    const float* W2     = (const float*)d_in[8];
    const float* b2     = (const float*)d_in[9];

    const int B = in_sizes[1] / 32;          // h0 is [B, 32]
    const int threads = 128;
    const long total = ((long)B / 2) * 8;    // 8 threads per row-pair
    const int blocks = (int)((total + threads - 1) / threads);
    ode_gru_kernel<<<blocks, threads>>>(inputs, h0, Wih, Whh, bih, bhh,
                                        W1, b1, W2, b2, (float*)d_out, B);
}

// round 6
// speedup vs baseline: 1.5272x; 1.5272x over previous
#include <cuda_runtime.h>

// GRU-ODE: B=32768 rows, T=28, DIM=H=32, 10-step RK4, RHS = 2-layer tanh MLP.
// R3 layout (4 lanes/row, 2 rows/thread, j-slice 8) + f32x2-packed FMAs.
// Anti-reg-explosion (R4/R5 lesson): src loop kept DYNAMIC (#pragma unroll 1)
// so ptxas can only hoist 8 k-iterations of weight loads, and launch_bounds
// minBlocks=3 caps regs at 170. Per k-iter/thread: 2 LDS.128 + 2 SHFL +
// 2 MOV64(alu) + 8 FFMA2 = 14 slots for 32 FMA-ops (R3 was 20).

#define TT 28
#define NSTEPS 10
typedef unsigned long long u64;

struct __align__(16) SW {
    float T1[1024], T2[1024];       // T[k*32+j] = W[j*32+k] (transposed)
    float Tih[3][1024], Thh[3][1024];
    float b1[32], b2[32];
    float br[32], bz[32], bni[32], bnh[32];  // GRU biases (r,z presummed)
};

__device__ __forceinline__ u64 splat2(float x) {
    u64 d; asm("mov.b64 %0, {%1, %1};" : "=l"(d) : "f"(x)); return d;
}
__device__ __forceinline__ float2 unpack2(u64 v) {
    float2 r; asm("mov.b64 {%0, %1}, %2;" : "=f"(r.x), "=f"(r.y) : "l"(v)); return r;
}
__device__ __forceinline__ u64 fma2(u64 a, u64 b, u64 c) {
    u64 d; asm("fma.rn.f32x2 %0, %1, %2, %3;" : "=l"(d) : "l"(a), "l"(b), "l"(c)); return d;
}

__device__ __forceinline__ float sigmoidf_fast(float x) {
    return __fdividef(1.0f, 1.0f + __expf(-x));
}
__device__ __forceinline__ float tanhf_fast(float x) {
    return 1.0f - __fdividef(2.0f, 1.0f + __expf(2.0f * x));
}

// acc[r][p] (f32x2 over j=(qoff+2p, qoff+2p+1)) += y[r][k] * T[k*32+qoff+..].
// y distributed 8/thread across the 4-lane quad; k = src*8 + m.
// src loop is dynamic on purpose: bounds ptxas load-hoisting to 8 k's.
__device__ __forceinline__ void mv2(const float* __restrict__ T, int qoff,
                                    const float (&y)[2][8], u64 (&a)[2][4]) {
#pragma unroll 1
    for (int src = 0; src < 4; ++src) {
#pragma unroll
        for (int m = 0; m < 8; ++m) {
            const int k = src * 8 + m;
            const ulonglong2 wlo = *reinterpret_cast<const ulonglong2*>(T + k * 32 + qoff);
            const ulonglong2 whi = *reinterpret_cast<const ulonglong2*>(T + k * 32 + qoff + 4);
            const u64 s0 = splat2(__shfl_sync(0xffffffffu, y[0][m], src, 4));
            const u64 s1 = splat2(__shfl_sync(0xffffffffu, y[1][m], src, 4));
            a[0][0] = fma2(s0, wlo.x, a[0][0]);
            a[0][1] = fma2(s0, wlo.y, a[0][1]);
            a[0][2] = fma2(s0, whi.x, a[0][2]);
            a[0][3] = fma2(s0, whi.y, a[0][3]);
            a[1][0] = fma2(s1, wlo.x, a[1][0]);
            a[1][1] = fma2(s1, wlo.y, a[1][1]);
            a[1][2] = fma2(s1, whi.x, a[1][2]);
            a[1][3] = fma2(s1, whi.y, a[1][3]);
        }
    }
}

// f = tanh(y @ W1^T + b1) @ W2^T + b2 for 2 rows (this thread's 8-j slice).
__device__ __forceinline__ void rhs2(const SW* __restrict__ s, int qoff,
                                     const float (&y)[2][8], float (&f)[2][8]) {
    u64 acc[2][4];
    {
        const ulonglong2 blo = *reinterpret_cast<const ulonglong2*>(s->b1 + qoff);
        const ulonglong2 bhi = *reinterpret_cast<const ulonglong2*>(s->b1 + qoff + 4);
        acc[0][0] = blo.x; acc[0][1] = blo.y; acc[0][2] = bhi.x; acc[0][3] = bhi.y;
        acc[1][0] = blo.x; acc[1][1] = blo.y; acc[1][2] = bhi.x; acc[1][3] = bhi.y;
    }
    mv2(s->T1, qoff, y, acc);
    float z[2][8];
#pragma unroll
    for (int r = 0; r < 2; ++r)
#pragma unroll
        for (int p = 0; p < 4; ++p) {
            const float2 v = unpack2(acc[r][p]);
            z[r][2 * p]     = tanhf_fast(v.x);
            z[r][2 * p + 1] = tanhf_fast(v.y);
        }
    {
        const ulonglong2 blo = *reinterpret_cast<const ulonglong2*>(s->b2 + qoff);
        const ulonglong2 bhi = *reinterpret_cast<const ulonglong2*>(s->b2 + qoff + 4);
        acc[0][0] = blo.x; acc[0][1] = blo.y; acc[0][2] = bhi.x; acc[0][3] = bhi.y;
        acc[1][0] = blo.x; acc[1][1] = blo.y; acc[1][2] = bhi.x; acc[1][3] = bhi.y;
    }
    mv2(s->T2, qoff, z, acc);
#pragma unroll
    for (int r = 0; r < 2; ++r)
#pragma unroll
        for (int p = 0; p < 4; ++p) {
            const float2 v = unpack2(acc[r][p]);
            f[r][2 * p] = v.x; f[r][2 * p + 1] = v.y;
        }
}

__device__ __forceinline__ void rk4(const SW* __restrict__ s, int qoff,
                                    float (&h)[2][8], float span) {
    const float dt = span * (1.0f / NSTEPS);
#pragma unroll 1
    for (int st = 0; st < NSTEPS; ++st) {
        float yt[2][8], ks[2][8], kc[2][8];
#pragma unroll
        for (int r = 0; r < 2; ++r)
#pragma unroll
            for (int j = 0; j < 8; ++j) { yt[r][j] = h[r][j]; ks[r][j] = 0.0f; }
#pragma unroll 1
        for (int sg = 0; sg < 4; ++sg) {
            rhs2(s, qoff, yt, kc);
            const float ws = (sg == 1 || sg == 2) ? 2.0f : 1.0f;
            const float cn = (sg < 2) ? 0.5f * dt : dt;
#pragma unroll
            for (int r = 0; r < 2; ++r)
#pragma unroll
                for (int j = 0; j < 8; ++j) {
                    ks[r][j] = fmaf(ws, kc[r][j], ks[r][j]);
                    yt[r][j] = fmaf(cn, kc[r][j], h[r][j]);  // extra at sg=3: harmless
                }
        }
#pragma unroll
        for (int r = 0; r < 2; ++r)
#pragma unroll
            for (int j = 0; j < 8; ++j)
                h[r][j] = fmaf(dt * (1.0f / 6.0f), ks[r][j], h[r][j]);
    }
}

// PyTorch-order GRU (r,z,n) on 2 rows, 8-j slice.
__device__ __forceinline__ void gru2(const SW* __restrict__ s, int qoff,
                                     float (&h)[2][8], const float (&x)[2][8]) {
    u64 a1[2][4], a2[2][4];
    float rg[2][8], zg[2][8];
    // r gate
    {
        const ulonglong2 blo = *reinterpret_cast<const ulonglong2*>(s->br + qoff);
        const ulonglong2 bhi = *reinterpret_cast<const ulonglong2*>(s->br + qoff + 4);
        a1[0][0] = blo.x; a1[0][1] = blo.y; a1[0][2] = bhi.x; a1[0][3] = bhi.y;
        a1[1][0] = blo.x; a1[1][1] = blo.y; a1[1][2] = bhi.x; a1[1][3] = bhi.y;
    }
    mv2(s->Tih[0], qoff, x, a1);
    mv2(s->Thh[0], qoff, h, a1);
#pragma unroll
    for (int r = 0; r < 2; ++r)
#pragma unroll
        for (int p = 0; p < 4; ++p) {
            const float2 v = unpack2(a1[r][p]);
            rg[r][2 * p]     = sigmoidf_fast(v.x);
            rg[r][2 * p + 1] = sigmoidf_fast(v.y);
        }
    // z gate
    {
        const ulonglong2 blo = *reinterpret_cast<const ulonglong2*>(s->bz + qoff);
        const ulonglong2 bhi = *reinterpret_cast<const ulonglong2*>(s->bz + qoff + 4);
        a1[0][0] = blo.x; a1[0][1] = blo.y; a1[0][2] = bhi.x; a1[0][3] = bhi.y;
        a1[1][0] = blo.x; a1[1][1] = blo.y; a1[1][2] = bhi.x; a1[1][3] = bhi.y;
    }
    mv2(s->Tih[1], qoff, x, a1);
    mv2(s->Thh[1], qoff, h, a1);
#pragma unroll
    for (int r = 0; r < 2; ++r)
#pragma unroll
        for (int p = 0; p < 4; ++p) {
            const float2 v = unpack2(a1[r][p]);
            zg[r][2 * p]     = sigmoidf_fast(v.x);
            zg[r][2 * p + 1] = sigmoidf_fast(v.y);
        }
    // n gate: input part (a1) and hidden part (a2) separately
    {
        const ulonglong2 ilo = *reinterpret_cast<const ulonglong2*>(s->bni + qoff);
        const ulonglong2 ihi = *reinterpret_cast<const ulonglong2*>(s->bni + qoff + 4);
        const ulonglong2 hlo = *reinterpret_cast<const ulonglong2*>(s->bnh + qoff);
        const ulonglong2 hhi = *reinterpret_cast<const ulonglong2*>(s->bnh + qoff + 4);
        a1[0][0] = ilo.x; a1[0][1] = ilo.y; a1[0][2] = ihi.x; a1[0][3] = ihi.y;
        a1[1][0] = ilo.x; a1[1][1] = ilo.y; a1[1][2] = ihi.x; a1[1][3] = ihi.y;
        a2[0][0] = hlo.x; a2[0][1] = hlo.y; a2[0][2] = hhi.x; a2[0][3] = hhi.y;
        a2[1][0] = hlo.x; a2[1][1] = hlo.y; a2[1][2] = hhi.x; a2[1][3] = hhi.y;
    }
    mv2(s->Tih[2], qoff, x, a1);
    mv2(s->Thh[2], qoff, h, a2);
#pragma unroll
    for (int r = 0; r < 2; ++r)
#pragma unroll
        for (int p = 0; p < 4; ++p) {
            const float2 gi = unpack2(a1[r][p]);
            const float2 gh = unpack2(a2[r][p]);
            const float n0 = tanhf_fast(gi.x + rg[r][2 * p] * gh.x);
            const float n1 = tanhf_fast(gi.y + rg[r][2 * p + 1] * gh.y);
            h[r][2 * p]     = n0 + zg[r][2 * p]     * (h[r][2 * p]     - n0);
            h[r][2 * p + 1] = n1 + zg[r][2 * p + 1] * (h[r][2 * p + 1] - n1);
        }
}

__device__ __forceinline__ void load8(const float* __restrict__ p, float (&v)[8]) {
    const float4 a = *reinterpret_cast<const float4*>(p);
    const float4 b = *reinterpret_cast<const float4*>(p + 4);
    v[0] = a.x; v[1] = a.y; v[2] = a.z; v[3] = a.w;
    v[4] = b.x; v[5] = b.y; v[6] = b.z; v[7] = b.w;
}

extern "C" __global__ void __launch_bounds__(128, 3)
ode_gru_kernel(const float* __restrict__ inputs, const float* __restrict__ h0,
               const float* __restrict__ Wih, const float* __restrict__ Whh,
               const float* __restrict__ bih, const float* __restrict__ bhh,
               const float* __restrict__ W1, const float* __restrict__ b1,
               const float* __restrict__ W2, const float* __restrict__ b2,
               float* __restrict__ out, int B) {
    __shared__ SW s;
    for (int i = threadIdx.x; i < 1024; i += blockDim.x) {
        const int j = i >> 5, k = i & 31;
        s.T1[k * 32 + j] = W1[i];
        s.T2[k * 32 + j] = W2[i];
    }
    for (int i = threadIdx.x; i < 3072; i += blockDim.x) {
        const int g = i >> 10, r = (i >> 5) & 31, k = i & 31;
        s.Tih[g][k * 32 + r] = Wih[i];
        s.Thh[g][k * 32 + r] = Whh[i];
    }
    for (int i = threadIdx.x; i < 32; i += blockDim.x) {
        s.b1[i]  = b1[i];            s.b2[i]  = b2[i];
        s.br[i]  = bih[i] + bhh[i];  s.bz[i]  = bih[32 + i] + bhh[32 + i];
        s.bni[i] = bih[64 + i];      s.bnh[i] = bhh[64 + i];
    }
    __syncthreads();

    const int gt   = blockIdx.x * blockDim.x + threadIdx.x;
    const int pair = gt >> 2;            // row-pair index (4 lanes each)
    const int qoff = (gt & 3) * 8;       // j-slice offset
    const int rowA = pair * 2;
    const int rowB = rowA + 1;
    if (rowB >= B) return;               // B even: uniform per warp

    float h[2][8];
    load8(h0 + (size_t)rowA * 32 + qoff, h[0]);
    load8(h0 + (size_t)rowB * 32 + qoff, h[1]);

    const float* xa = inputs + (size_t)rowA * TT * 32 + qoff;
    const float* xb = inputs + (size_t)rowB * TT * 32 + qoff;

    // initial integration over [0, 1]
    rk4(&s, qoff, h, 1.0f);

#pragma unroll 1
    for (int t = 0; t < TT; ++t) {
        float x[2][8];
        load8(xa + t * 32, x[0]);
        load8(xb + t * 32, x[1]);
        gru2(&s, qoff, h, x);
        if (t < TT - 1) rk4(&s, qoff, h, 1.0f);
    }

    // h_start -> out[0], then 14-unit integration -> out[1]
#pragma unroll
    for (int j = 0; j < 8; ++j) {
        out[(size_t)rowA * 32 + qoff + j] = fmaxf(h[0][j], 0.0f);
        out[(size_t)rowB * 32 + qoff + j] = fmaxf(h[1][j], 0.0f);
    }
    rk4(&s, qoff, h, 14.0f);
#pragma unroll
    for (int j = 0; j < 8; ++j) {
        out[(size_t)B * 32 + (size_t)rowA * 32 + qoff + j] = fmaxf(h[0][j], 0.0f);
        out[(size_t)B * 32 + (size_t)rowB * 32 + qoff + j] = fmaxf(h[1][j], 0.0f);
    }
}

extern "C" void kernel_launch(void* const* d_in, const int* in_sizes, int n_in,
                              void* d_out, int out_size) {
    const float* inputs = (const float*)d_in[0];
    const float* h0     = (const float*)d_in[1];
    const float* Wih    = (const float*)d_in[2];
    const float* Whh    = (const float*)d_in[3];
    const float* bih    = (const float*)d_in[4];
    const float* bhh    = (const float*)d_in[5];
    const float* W1     = (const float*)d_in[6];
    const float* b1     = (const float*)d_in[7];
    const float* W2     = (const float*)d_in[8];
    const float* b2     = (const float*)d_in[9];

    const int B = in_sizes[1] / 32;          // h0 is [B, 32]
    const int threads = 128;
    const long total = ((long)B / 2) * 4;    // 4 threads per row-pair
    const int blocks = (int)((total + threads - 1) / threads);
    ode_gru_kernel<<<blocks, threads>>>(inputs, h0, Wih, Whh, bih, bhh,
                                        W1, b1, W2, b2, (float*)d_out, B);
}

// round 7
// speedup vs baseline: 1.6277x; 1.0659x over previous
#include <cuda_runtime.h>

// GRU-ODE: B=32768 rows, T=28, DIM=H=32, 10-step RK4, RHS = 2-layer tanh MLP.
// Quad layout (4 lanes/row-pair, 2 rows/thread, j-slice 8) + f32x2 FMAs.
// R7 change: width-4 SHUFFLES replaced by a padded smem y-exchange
// (pair stride 68 floats -> conflict-free LDS.128 of 4 k's at a time).
// Per k-iter/warp: 2 weight-LDS wf + 0.5 y-LDS wf + 0.5 STS wf (~3.0)
// vs R6's 2 LDS + 2 SHFL (4.0) on the saturated l1tex pipe.

#define TT 28
#define NSTEPS 10
typedef unsigned long long u64;

#define PAIR_STRIDE 68   // 64 floats data + 4 pad -> pairs hit distinct 16B sectors

struct __align__(16) SW {
    float T1[1024], T2[1024];       // T[k*32+j] = W[j*32+k] (transposed)
    float Tih[3][1024], Thh[3][1024];
    float b1[32], b2[32];
    float br[32], bz[32], bni[32], bnh[32];  // GRU biases (r,z presummed)
};

__device__ __forceinline__ u64 splat2(float x) {
    u64 d; asm("mov.b64 %0, {%1, %1};" : "=l"(d) : "f"(x)); return d;
}
__device__ __forceinline__ float2 unpack2(u64 v) {
    float2 r; asm("mov.b64 {%0, %1}, %2;" : "=f"(r.x), "=f"(r.y) : "l"(v)); return r;
}
__device__ __forceinline__ u64 fma2(u64 a, u64 b, u64 c) {
    u64 d; asm("fma.rn.f32x2 %0, %1, %2, %3;" : "=l"(d) : "l"(a), "l"(b), "l"(c)); return d;
}

__device__ __forceinline__ float sigmoidf_fast(float x) {
    return __fdividef(1.0f, 1.0f + __expf(-x));
}
__device__ __forceinline__ float tanhf_fast(float x) {
    return 1.0f - __fdividef(2.0f, 1.0f + __expf(2.0f * x));
}

// acc[r][p] (f32x2 over j=(qoff+2p,qoff+2p+1)) += y[r][k] * T[k*32+qoff+..].
// Input y is exchanged through the per-pair smem buffer pb (stride 68):
// store both rows' slices, syncwarp, then every lane streams y 4-k per LDS.128.
__device__ __forceinline__ void mv2s(const float* __restrict__ T, int qoff,
                                     float* __restrict__ pb,
                                     const float (&y)[2][8], u64 (&a)[2][4]) {
    *reinterpret_cast<float4*>(pb + qoff)
        = make_float4(y[0][0], y[0][1], y[0][2], y[0][3]);
    *reinterpret_cast<float4*>(pb + qoff + 4)
        = make_float4(y[0][4], y[0][5], y[0][6], y[0][7]);
    *reinterpret_cast<float4*>(pb + 32 + qoff)
        = make_float4(y[1][0], y[1][1], y[1][2], y[1][3]);
    *reinterpret_cast<float4*>(pb + 32 + qoff + 4)
        = make_float4(y[1][4], y[1][5], y[1][6], y[1][7]);
    __syncwarp();
#pragma unroll 1
    for (int src = 0; src < 4; ++src) {           // dynamic: bounds reg hoisting
#pragma unroll
        for (int half = 0; half < 2; ++half) {
            const int k0 = src * 8 + half * 4;
            const float4 ya = *reinterpret_cast<const float4*>(pb + k0);
            const float4 yb = *reinterpret_cast<const float4*>(pb + 32 + k0);
            const float ya_[4] = {ya.x, ya.y, ya.z, ya.w};
            const float yb_[4] = {yb.x, yb.y, yb.z, yb.w};
#pragma unroll
            for (int m = 0; m < 4; ++m) {
                const int k = k0 + m;
                const ulonglong2 wlo = *reinterpret_cast<const ulonglong2*>(T + k * 32 + qoff);
                const ulonglong2 whi = *reinterpret_cast<const ulonglong2*>(T + k * 32 + qoff + 4);
                const u64 s0 = splat2(ya_[m]);
                const u64 s1 = splat2(yb_[m]);
                a[0][0] = fma2(s0, wlo.x, a[0][0]);
                a[0][1] = fma2(s0, wlo.y, a[0][1]);
                a[0][2] = fma2(s0, whi.x, a[0][2]);
                a[0][3] = fma2(s0, whi.y, a[0][3]);
                a[1][0] = fma2(s1, wlo.x, a[1][0]);
                a[1][1] = fma2(s1, wlo.y, a[1][1]);
                a[1][2] = fma2(s1, whi.x, a[1][2]);
                a[1][3] = fma2(s1, whi.y, a[1][3]);
            }
        }
    }
    __syncwarp();
}

__device__ __forceinline__ void initacc(const float* __restrict__ b, int qoff,
                                        u64 (&a)[2][4]) {
    const ulonglong2 blo = *reinterpret_cast<const ulonglong2*>(b + qoff);
    const ulonglong2 bhi = *reinterpret_cast<const ulonglong2*>(b + qoff + 4);
    a[0][0] = blo.x; a[0][1] = blo.y; a[0][2] = bhi.x; a[0][3] = bhi.y;
    a[1][0] = blo.x; a[1][1] = blo.y; a[1][2] = bhi.x; a[1][3] = bhi.y;
}

// f = tanh(y @ W1^T + b1) @ W2^T + b2 for 2 rows (this thread's 8-j slice).
__device__ __forceinline__ void rhs2(const SW* __restrict__ s, int qoff,
                                     float* __restrict__ pb,
                                     const float (&y)[2][8], float (&f)[2][8]) {
    u64 acc[2][4];
    initacc(s->b1, qoff, acc);
    mv2s(s->T1, qoff, pb, y, acc);
    float z[2][8];
#pragma unroll
    for (int r = 0; r < 2; ++r)
#pragma unroll
        for (int p = 0; p < 4; ++p) {
            const float2 v = unpack2(acc[r][p]);
            z[r][2 * p]     = tanhf_fast(v.x);
            z[r][2 * p + 1] = tanhf_fast(v.y);
        }
    initacc(s->b2, qoff, acc);
    mv2s(s->T2, qoff, pb, z, acc);
#pragma unroll
    for (int r = 0; r < 2; ++r)
#pragma unroll
        for (int p = 0; p < 4; ++p) {
            const float2 v = unpack2(acc[r][p]);
            f[r][2 * p] = v.x; f[r][2 * p + 1] = v.y;
        }
}

__device__ __forceinline__ void rk4(const SW* __restrict__ s, int qoff,
                                    float* __restrict__ pb,
                                    float (&h)[2][8], float span) {
    const float dt = span * (1.0f / NSTEPS);
#pragma unroll 1
    for (int st = 0; st < NSTEPS; ++st) {
        float yt[2][8], ks[2][8], kc[2][8];
#pragma unroll
        for (int r = 0; r < 2; ++r)
#pragma unroll
            for (int j = 0; j < 8; ++j) { yt[r][j] = h[r][j]; ks[r][j] = 0.0f; }
#pragma unroll 1
        for (int sg = 0; sg < 4; ++sg) {
            rhs2(s, qoff, pb, yt, kc);
            const float ws = (sg == 1 || sg == 2) ? 2.0f : 1.0f;
            const float cn = (sg < 2) ? 0.5f * dt : dt;
#pragma unroll
            for (int r = 0; r < 2; ++r)
#pragma unroll
                for (int j = 0; j < 8; ++j) {
                    ks[r][j] = fmaf(ws, kc[r][j], ks[r][j]);
                    yt[r][j] = fmaf(cn, kc[r][j], h[r][j]);  // extra at sg=3: harmless
                }
        }
#pragma unroll
        for (int r = 0; r < 2; ++r)
#pragma unroll
            for (int j = 0; j < 8; ++j)
                h[r][j] = fmaf(dt * (1.0f / 6.0f), ks[r][j], h[r][j]);
    }
}

// PyTorch-order GRU (r,z,n) on 2 rows, 8-j slice.
__device__ __forceinline__ void gru2(const SW* __restrict__ s, int qoff,
                                     float* __restrict__ pb,
                                     float (&h)[2][8], const float (&x)[2][8]) {
    u64 a1[2][4], a2[2][4];
    float rg[2][8], zg[2][8];
    // r gate
    initacc(s->br, qoff, a1);
    mv2s(s->Tih[0], qoff, pb, x, a1);
    mv2s(s->Thh[0], qoff, pb, h, a1);
#pragma unroll
    for (int r = 0; r < 2; ++r)
#pragma unroll
        for (int p = 0; p < 4; ++p) {
            const float2 v = unpack2(a1[r][p]);
            rg[r][2 * p]     = sigmoidf_fast(v.x);
            rg[r][2 * p + 1] = sigmoidf_fast(v.y);
        }
    // z gate
    initacc(s->bz, qoff, a1);
    mv2s(s->Tih[1], qoff, pb, x, a1);
    mv2s(s->Thh[1], qoff, pb, h, a1);
#pragma unroll
    for (int r = 0; r < 2; ++r)
#pragma unroll
        for (int p = 0; p < 4; ++p) {
            const float2 v = unpack2(a1[r][p]);
            zg[r][2 * p]     = sigmoidf_fast(v.x);
            zg[r][2 * p + 1] = sigmoidf_fast(v.y);
        }
    // n gate: input part (a1) and hidden part (a2)
    initacc(s->bni, qoff, a1);
    mv2s(s->Tih[2], qoff, pb, x, a1);
    initacc(s->bnh, qoff, a2);
    mv2s(s->Thh[2], qoff, pb, h, a2);
#pragma unroll
    for (int r = 0; r < 2; ++r)
#pragma unroll
        for (int p = 0; p < 4; ++p) {
            const float2 gi = unpack2(a1[r][p]);
            const float2 gh = unpack2(a2[r][p]);
            const float n0 = tanhf_fast(gi.x + rg[r][2 * p] * gh.x);
            const float n1 = tanhf_fast(gi.y + rg[r][2 * p + 1] * gh.y);
            h[r][2 * p]     = n0 + zg[r][2 * p]     * (h[r][2 * p]     - n0);
            h[r][2 * p + 1] = n1 + zg[r][2 * p + 1] * (h[r][2 * p + 1] - n1);
        }
}

__device__ __forceinline__ void load8(const float* __restrict__ p, float (&v)[8]) {
    const float4 a = *reinterpret_cast<const float4*>(p);
    const float4 b = *reinterpret_cast<const float4*>(p + 4);
    v[0] = a.x; v[1] = a.y; v[2] = a.z; v[3] = a.w;
    v[4] = b.x; v[5] = b.y; v[6] = b.z; v[7] = b.w;
}

extern "C" __global__ void __launch_bounds__(128, 3)
ode_gru_kernel(const float* __restrict__ inputs, const float* __restrict__ h0,
               const float* __restrict__ Wih, const float* __restrict__ Whh,
               const float* __restrict__ bih, const float* __restrict__ bhh,
               const float* __restrict__ W1, const float* __restrict__ b1,
               const float* __restrict__ W2, const float* __restrict__ b2,
               float* __restrict__ out, int B) {
    __shared__ SW s;
    __shared__ float ybuf[32 * PAIR_STRIDE];   // 32 pairs per 128-thread CTA

    for (int i = threadIdx.x; i < 1024; i += blockDim.x) {
        const int j = i >> 5, k = i & 31;
        s.T1[k * 32 + j] = W1[i];
        s.T2[k * 32 + j] = W2[i];
    }
    for (int i = threadIdx.x; i < 3072; i += blockDim.x) {
        const int g = i >> 10, r = (i >> 5) & 31, k = i & 31;
        s.Tih[g][k * 32 + r] = Wih[i];
        s.Thh[g][k * 32 + r] = Whh[i];
    }
    for (int i = threadIdx.x; i < 32; i += blockDim.x) {
        s.b1[i]  = b1[i];            s.b2[i]  = b2[i];
        s.br[i]  = bih[i] + bhh[i];  s.bz[i]  = bih[32 + i] + bhh[32 + i];
        s.bni[i] = bih[64 + i];      s.bnh[i] = bhh[64 + i];
    }
    __syncthreads();

    const int gt   = blockIdx.x * blockDim.x + threadIdx.x;
    const int pair = gt >> 2;            // row-pair index (4 lanes each)
    const int qoff = (gt & 3) * 8;       // j-slice offset
    const int rowA = pair * 2;
    const int rowB = rowA + 1;
    if (rowB >= B) return;               // grid sized exactly: never taken

    float* pb = ybuf + (threadIdx.x >> 2) * PAIR_STRIDE;

    float h[2][8];
    load8(h0 + (size_t)rowA * 32 + qoff, h[0]);
    load8(h0 + (size_t)rowB * 32 + qoff, h[1]);

    const float* xa = inputs + (size_t)rowA * TT * 32 + qoff;
    const float* xb = inputs + (size_t)rowB * TT * 32 + qoff;

    // initial integration over [0, 1]
    rk4(&s, qoff, pb, h, 1.0f);

#pragma unroll 1
    for (int t = 0; t < TT; ++t) {
        float x[2][8];
        load8(xa + t * 32, x[0]);
        load8(xb + t * 32, x[1]);
        gru2(&s, qoff, pb, h, x);
        if (t < TT - 1) rk4(&s, qoff, pb, h, 1.0f);
    }

    // h_start -> out[0], then 14-unit integration -> out[1]
#pragma unroll
    for (int j = 0; j < 8; ++j) {
        out[(size_t)rowA * 32 + qoff + j] = fmaxf(h[0][j], 0.0f);
        out[(size_t)rowB * 32 + qoff + j] = fmaxf(h[1][j], 0.0f);
    }
    rk4(&s, qoff, pb, h, 14.0f);
#pragma unroll
    for (int j = 0; j < 8; ++j) {
        out[(size_t)B * 32 + (size_t)rowA * 32 + qoff + j] = fmaxf(h[0][j], 0.0f);
        out[(size_t)B * 32 + (size_t)rowB * 32 + qoff + j] = fmaxf(h[1][j], 0.0f);
    }
}

extern "C" void kernel_launch(void* const* d_in, const int* in_sizes, int n_in,
                              void* d_out, int out_size) {
    const float* inputs = (const float*)d_in[0];
    const float* h0     = (const float*)d_in[1];
    const float* Wih    = (const float*)d_in[2];
    const float* Whh    = (const float*)d_in[3];
    const float* bih    = (const float*)d_in[4];
    const float* bhh    = (const float*)d_in[5];
    const float* W1     = (const float*)d_in[6];
    const float* b1     = (const float*)d_in[7];
    const float* W2     = (const float*)d_in[8];
    const float* b2     = (const float*)d_in[9];

    const int B = in_sizes[1] / 32;          // h0 is [B, 32]
    const int threads = 128;
    const long total = ((long)B / 2) * 4;    // 4 threads per row-pair
    const int blocks = (int)((total + threads - 1) / threads);
    ode_gru_kernel<<<blocks, threads>>>(inputs, h0, Wih, Whh, bih, bhh,
                                        W1, b1, W2, b2, (float*)d_out, B);
}

// round 8
// speedup vs baseline: 1.7053x; 1.0476x over previous
#include <cuda_runtime.h>

// GRU-ODE: B=32768 rows, T=28, DIM=H=32, 10-step RK4, RHS = 2-layer tanh MLP.
// OCT layout: 8 lanes per row-pair (j-slice 4), 2 rows/thread, f32x2 FMAs.
// One weight LDS.128 per k serves the whole row (128B unique per warp) ->
// 32 weight-LDS/matvec vs quad's 64: targets the measured l1tex binder.
// y exchanged via double-buffered padded smem (1 syncwarp per matvec).

#define TT 28
#define NSTEPS 10
typedef unsigned long long u64;

#define GRP_STRIDE 68        // 64 floats data + 4 pad per oct-group buffer
#define SLOT_STRIDE (16 * GRP_STRIDE)

struct __align__(16) SW {
    float T1[1024], T2[1024];       // T[k*32+j] = W[j*32+k] (transposed)
    float Tih[3][1024], Thh[3][1024];
    float b1[32], b2[32];
    float br[32], bz[32], bni[32], bnh[32];  // GRU biases (r,z presummed)
};

__device__ __forceinline__ u64 splat2(float x) {
    u64 d; asm("mov.b64 %0, {%1, %1};" : "=l"(d) : "f"(x)); return d;
}
__device__ __forceinline__ float2 unpack2(u64 v) {
    float2 r; asm("mov.b64 {%0, %1}, %2;" : "=f"(r.x), "=f"(r.y) : "l"(v)); return r;
}
__device__ __forceinline__ u64 fma2(u64 a, u64 b, u64 c) {
    u64 d; asm("fma.rn.f32x2 %0, %1, %2, %3;" : "=l"(d) : "l"(a), "l"(b), "l"(c)); return d;
}

__device__ __forceinline__ float sigmoidf_fast(float x) {
    return __fdividef(1.0f, 1.0f + __expf(-x));
}
__device__ __forceinline__ float tanhf_fast(float x) {
    return 1.0f - __fdividef(2.0f, 1.0f + __expf(2.0f * x));
}

// acc[r][p] (f32x2 over j=(ooff+2p,ooff+2p+1)) += y[r][k] * T[k*32+ooff+..].
// y distributed 4/thread across the 8-lane oct, exchanged via slot buffer pb.
// Exactly one __syncwarp: WAR on pb is covered by the NEXT matvec's sync
// (callers strictly alternate between two slots).
__device__ __forceinline__ void mv2o(const float* __restrict__ T, int ooff,
                                     float* __restrict__ pb,
                                     const float (&y)[2][4], u64 (&a)[2][2]) {
    *reinterpret_cast<float4*>(pb + ooff)
        = make_float4(y[0][0], y[0][1], y[0][2], y[0][3]);
    *reinterpret_cast<float4*>(pb + 32 + ooff)
        = make_float4(y[1][0], y[1][1], y[1][2], y[1][3]);
    __syncwarp();
#pragma unroll 1
    for (int src = 0; src < 8; ++src) {          // dynamic: bounds reg hoisting
        const int k0 = src * 4;
        const float4 ya = *reinterpret_cast<const float4*>(pb + k0);
        const float4 yb = *reinterpret_cast<const float4*>(pb + 32 + k0);
        const float ya_[4] = {ya.x, ya.y, ya.z, ya.w};
        const float yb_[4] = {yb.x, yb.y, yb.z, yb.w};
#pragma unroll
        for (int m = 0; m < 4; ++m) {
            const ulonglong2 w = *reinterpret_cast<const ulonglong2*>(T + (k0 + m) * 32 + ooff);
            const u64 s0 = splat2(ya_[m]);
            const u64 s1 = splat2(yb_[m]);
            a[0][0] = fma2(s0, w.x, a[0][0]);
            a[0][1] = fma2(s0, w.y, a[0][1]);
            a[1][0] = fma2(s1, w.x, a[1][0]);
            a[1][1] = fma2(s1, w.y, a[1][1]);
        }
    }
}

__device__ __forceinline__ void initacc(const float* __restrict__ b, int ooff,
                                        u64 (&a)[2][2]) {
    const ulonglong2 bb = *reinterpret_cast<const ulonglong2*>(b + ooff);
    a[0][0] = bb.x; a[0][1] = bb.y;
    a[1][0] = bb.x; a[1][1] = bb.y;
}

// f = tanh(y @ W1^T + b1) @ W2^T + b2 for 2 rows (this thread's 4-j slice).
__device__ __forceinline__ void rhs2(const SW* __restrict__ s, int ooff,
                                     float* __restrict__ yb0, float* __restrict__ yb1,
                                     const float (&y)[2][4], float (&f)[2][4]) {
    u64 acc[2][2];
    initacc(s->b1, ooff, acc);
    mv2o(s->T1, ooff, yb0, y, acc);
    float z[2][4];
#pragma unroll
    for (int r = 0; r < 2; ++r)
#pragma unroll
        for (int p = 0; p < 2; ++p) {
            const float2 v = unpack2(acc[r][p]);
            z[r][2 * p]     = tanhf_fast(v.x);
            z[r][2 * p + 1] = tanhf_fast(v.y);
        }
    initacc(s->b2, ooff, acc);
    mv2o(s->T2, ooff, yb1, z, acc);
#pragma unroll
    for (int r = 0; r < 2; ++r)
#pragma unroll
        for (int p = 0; p < 2; ++p) {
            const float2 v = unpack2(acc[r][p]);
            f[r][2 * p] = v.x; f[r][2 * p + 1] = v.y;
        }
}

__device__ __forceinline__ void rk4(const SW* __restrict__ s, int ooff,
                                    float* __restrict__ yb0, float* __restrict__ yb1,
                                    float (&h)[2][4], float span) {
    const float dt = span * (1.0f / NSTEPS);
#pragma unroll 1
    for (int st = 0; st < NSTEPS; ++st) {
        float yt[2][4], ks[2][4], kc[2][4];
#pragma unroll
        for (int r = 0; r < 2; ++r)
#pragma unroll
            for (int j = 0; j < 4; ++j) { yt[r][j] = h[r][j]; ks[r][j] = 0.0f; }
#pragma unroll 1
        for (int sg = 0; sg < 4; ++sg) {
            rhs2(s, ooff, yb0, yb1, yt, kc);
            const float ws = (sg == 1 || sg == 2) ? 2.0f : 1.0f;
            const float cn = (sg < 2) ? 0.5f * dt : dt;
#pragma unroll
            for (int r = 0; r < 2; ++r)
#pragma unroll
                for (int j = 0; j < 4; ++j) {
                    ks[r][j] = fmaf(ws, kc[r][j], ks[r][j]);
                    yt[r][j] = fmaf(cn, kc[r][j], h[r][j]);  // extra at sg=3: harmless
                }
        }
#pragma unroll
        for (int r = 0; r < 2; ++r)
#pragma unroll
            for (int j = 0; j < 4; ++j)
                h[r][j] = fmaf(dt * (1.0f / 6.0f), ks[r][j], h[r][j]);
    }
}

// PyTorch-order GRU (r,z,n) on 2 rows, 4-j slice.
__device__ __forceinline__ void gru2(const SW* __restrict__ s, int ooff,
                                     float* __restrict__ yb0, float* __restrict__ yb1,
                                     float (&h)[2][4], const float (&x)[2][4]) {
    u64 a1[2][2], a2[2][2];
    float rg[2][4], zg[2][4];
    // r gate
    initacc(s->br, ooff, a1);
    mv2o(s->Tih[0], ooff, yb0, x, a1);
    mv2o(s->Thh[0], ooff, yb1, h, a1);
#pragma unroll
    for (int r = 0; r < 2; ++r)
#pragma unroll
        for (int p = 0; p < 2; ++p) {
            const float2 v = unpack2(a1[r][p]);
            rg[r][2 * p]     = sigmoidf_fast(v.x);
            rg[r][2 * p + 1] = sigmoidf_fast(v.y);
        }
    // z gate
    initacc(s->bz, ooff, a1);
    mv2o(s->Tih[1], ooff, yb0, x, a1);
    mv2o(s->Thh[1], ooff, yb1, h, a1);
#pragma unroll
    for (int r = 0; r < 2; ++r)
#pragma unroll
        for (int p = 0; p < 2; ++p) {
            const float2 v = unpack2(a1[r][p]);
            zg[r][2 * p]     = sigmoidf_fast(v.x);
            zg[r][2 * p + 1] = sigmoidf_fast(v.y);
        }
    // n gate: input part (a1) and hidden part (a2)
    initacc(s->bni, ooff, a1);
    mv2o(s->Tih[2], ooff, yb0, x, a1);
    initacc(s->bnh, ooff, a2);
    mv2o(s->Thh[2], ooff, yb1, h, a2);
#pragma unroll
    for (int r = 0; r < 2; ++r)
#pragma unroll
        for (int p = 0; p < 2; ++p) {
            const float2 gi = unpack2(a1[r][p]);
            const float2 gh = unpack2(a2[r][p]);
            const float n0 = tanhf_fast(gi.x + rg[r][2 * p] * gh.x);
            const float n1 = tanhf_fast(gi.y + rg[r][2 * p + 1] * gh.y);
            h[r][2 * p]     = n0 + zg[r][2 * p]     * (h[r][2 * p]     - n0);
            h[r][2 * p + 1] = n1 + zg[r][2 * p + 1] * (h[r][2 * p + 1] - n1);
        }
}

__device__ __forceinline__ void load4(const float* __restrict__ p, float (&v)[4]) {
    const float4 a = *reinterpret_cast<const float4*>(p);
    v[0] = a.x; v[1] = a.y; v[2] = a.z; v[3] = a.w;
}

extern "C" __global__ void __launch_bounds__(128, 4)
ode_gru_kernel(const float* __restrict__ inputs, const float* __restrict__ h0,
               const float* __restrict__ Wih, const float* __restrict__ Whh,
               const float* __restrict__ bih, const float* __restrict__ bhh,
               const float* __restrict__ W1, const float* __restrict__ b1,
               const float* __restrict__ W2, const float* __restrict__ b2,
               float* __restrict__ out, int B) {
    __shared__ SW s;
    __shared__ float ybuf[2 * SLOT_STRIDE];   // 2 slots x 16 oct-groups

    for (int i = threadIdx.x; i < 1024; i += blockDim.x) {
        const int j = i >> 5, k = i & 31;
        s.T1[k * 32 + j] = W1[i];
        s.T2[k * 32 + j] = W2[i];
    }
    for (int i = threadIdx.x; i < 3072; i += blockDim.x) {
        const int g = i >> 10, r = (i >> 5) & 31, k = i & 31;
        s.Tih[g][k * 32 + r] = Wih[i];
        s.Thh[g][k * 32 + r] = Whh[i];
    }
    for (int i = threadIdx.x; i < 32; i += blockDim.x) {
        s.b1[i]  = b1[i];            s.b2[i]  = b2[i];
        s.br[i]  = bih[i] + bhh[i];  s.bz[i]  = bih[32 + i] + bhh[32 + i];
        s.bni[i] = bih[64 + i];      s.bnh[i] = bhh[64 + i];
    }
    __syncthreads();

    const int gt   = blockIdx.x * blockDim.x + threadIdx.x;
    const int pair = gt >> 3;            // row-pair index (8 lanes each)
    const int ooff = (gt & 7) * 4;       // j-slice offset
    const int rowA = pair * 2;
    const int rowB = rowA + 1;
    if (rowB >= B) return;               // grid sized exactly: never taken

    const int grp = threadIdx.x >> 3;    // oct-group within CTA (0..15)
    float* yb0 = ybuf + grp * GRP_STRIDE;
    float* yb1 = ybuf + SLOT_STRIDE + grp * GRP_STRIDE;

    float h[2][4];
    load4(h0 + (size_t)rowA * 32 + ooff, h[0]);
    load4(h0 + (size_t)rowB * 32 + ooff, h[1]);

    const float* xa = inputs + (size_t)rowA * TT * 32 + ooff;
    const float* xb = inputs + (size_t)rowB * TT * 32 + ooff;

    // initial integration over [0, 1]
    rk4(&s, ooff, yb0, yb1, h, 1.0f);

#pragma unroll 1
    for (int t = 0; t < TT; ++t) {
        float x[2][4];
        load4(xa + t * 32, x[0]);
        load4(xb + t * 32, x[1]);
        gru2(&s, ooff, yb0, yb1, h, x);
        if (t < TT - 1) rk4(&s, ooff, yb0, yb1, h, 1.0f);
    }

    // h_start -> out[0], then 14-unit integration -> out[1]
    {
        float4 oa = make_float4(fmaxf(h[0][0], 0.0f), fmaxf(h[0][1], 0.0f),
                                fmaxf(h[0][2], 0.0f), fmaxf(h[0][3], 0.0f));
        float4 ob = make_float4(fmaxf(h[1][0], 0.0f), fmaxf(h[1][1], 0.0f),
                                fmaxf(h[1][2], 0.0f), fmaxf(h[1][3], 0.0f));
        *reinterpret_cast<float4*>(out + (size_t)rowA * 32 + ooff) = oa;
        *reinterpret_cast<float4*>(out + (size_t)rowB * 32 + ooff) = ob;
    }
    rk4(&s, ooff, yb0, yb1, h, 14.0f);
    {
        float4 oa = make_float4(fmaxf(h[0][0], 0.0f), fmaxf(h[0][1], 0.0f),
                                fmaxf(h[0][2], 0.0f), fmaxf(h[0][3], 0.0f));
        float4 ob = make_float4(fmaxf(h[1][0], 0.0f), fmaxf(h[1][1], 0.0f),
                                fmaxf(h[1][2], 0.0f), fmaxf(h[1][3], 0.0f));
        *reinterpret_cast<float4*>(out + (size_t)B * 32 + (size_t)rowA * 32 + ooff) = oa;
        *reinterpret_cast<float4*>(out + (size_t)B * 32 + (size_t)rowB * 32 + ooff) = ob;
    }
}

extern "C" void kernel_launch(void* const* d_in, const int* in_sizes, int n_in,
                              void* d_out, int out_size) {
    const float* inputs = (const float*)d_in[0];
    const float* h0     = (const float*)d_in[1];
    const float* Wih    = (const float*)d_in[2];
    const float* Whh    = (const float*)d_in[3];
    const float* bih    = (const float*)d_in[4];
    const float* bhh    = (const float*)d_in[5];
    const float* W1     = (const float*)d_in[6];
    const float* b1     = (const float*)d_in[7];
    const float* W2     = (const float*)d_in[8];
    const float* b2     = (const float*)d_in[9];

    const int B = in_sizes[1] / 32;          // h0 is [B, 32]
    const int threads = 128;
    const long total = ((long)B / 2) * 8;    // 8 threads per row-pair
    const int blocks = (int)((total + threads - 1) / threads);
    ode_gru_kernel<<<blocks, threads>>>(inputs, h0, Wih, Whh, bih, bhh,
                                        W1, b1, W2, b2, (float*)d_out, B);
}

// round 10
// speedup vs baseline: 2.1063x; 1.2351x over previous
#include <cuda_runtime.h>

// GRU-ODE: B=32768 rows, T=28, DIM=H=32, 10-step RK4, RHS = 2-layer tanh MLP.
// OCT layout, R=4: 8 lanes per 4-row group (j-slice 4), f32x2 FMAs.
// l1tex binder model: smem->RF charges requested bytes (no broadcast dedup);
// traffic/row = 4KB/R (weights) + 128B*lanes (y). R=4,L=8 -> 2.1KB/row vs
// R8's 3.2KB. Per k/thread: 1 w-LDS.128 + 4 splat MOV + 8 FFMA2 = 16 FMA x4 rows.

#define TT 28
#define NSTEPS 10
typedef unsigned long long u64;

#define GRP_STRIDE 132       // 4 rows x 32 floats + 4 pad (group offsets spread banks)

struct __align__(16) SW {
    float T1[1024], T2[1024];       // T[k*32+j] = W[j*32+k] (transposed)
    float Tih[3][1024], Thh[3][1024];
    float b1[32], b2[32];
    float br[32], bz[32], bni[32], bnh[32];  // GRU biases (r,z presummed)
};

__device__ __forceinline__ u64 splat2(float x) {
    u64 d; asm("mov.b64 %0, {%1, %1};" : "=l"(d) : "f"(x)); return d;
}
__device__ __forceinline__ float2 unpack2(u64 v) {
    float2 r; asm("mov.b64 {%0, %1}, %2;" : "=f"(r.x), "=f"(r.y) : "l"(v)); return r;
}
__device__ __forceinline__ u64 fma2(u64 a, u64 b, u64 c) {
    u64 d; asm("fma.rn.f32x2 %0, %1, %2, %3;" : "=l"(d) : "l"(a), "l"(b), "l"(c)); return d;
}

__device__ __forceinline__ float sigmoidf_fast(float x) {
    return __fdividef(1.0f, 1.0f + __expf(-x));
}
__device__ __forceinline__ float tanhf_fast(float x) {
    return 1.0f - __fdividef(2.0f, 1.0f + __expf(2.0f * x));
}

// acc[r][p] (f32x2 over j=(ooff+2p,ooff+2p+1)) += y[r][k] * T[k*32+ooff+..],
// r = 0..3 rows. y exchanged via group smem buffer pb (pb[r*32 + k]).
// Two syncwarps (single-slot buffer): after stores, and after last load.
__device__ __forceinline__ void mv4o(const float* __restrict__ T, int ooff,
                                     float* __restrict__ pb,
                                     const float (&y)[4][4], u64 (&a)[4][2]) {
#pragma unroll
    for (int r = 0; r < 4; ++r)
        *reinterpret_cast<float4*>(pb + r * 32 + ooff)
            = make_float4(y[r][0], y[r][1], y[r][2], y[r][3]);
    __syncwarp();
#pragma unroll 1
    for (int src = 0; src < 8; ++src) {          // dynamic: bounds reg hoisting
        const int k0 = src * 4;
        float4 yv0 = *reinterpret_cast<const float4*>(pb + 0 * 32 + k0);
        float4 yv1 = *reinterpret_cast<const float4*>(pb + 1 * 32 + k0);
        float4 yv2 = *reinterpret_cast<const float4*>(pb + 2 * 32 + k0);
        float4 yv3 = *reinterpret_cast<const float4*>(pb + 3 * 32 + k0);
        const float ym[4][4] = {
            {yv0.x, yv0.y, yv0.z, yv0.w},
            {yv1.x, yv1.y, yv1.z, yv1.w},
            {yv2.x, yv2.y, yv2.z, yv2.w},
            {yv3.x, yv3.y, yv3.z, yv3.w}};
#pragma unroll
        for (int m = 0; m < 4; ++m) {
            const ulonglong2 w = *reinterpret_cast<const ulonglong2*>(T + (k0 + m) * 32 + ooff);
#pragma unroll
            for (int r = 0; r < 4; ++r) {
                const u64 s = splat2(ym[r][m]);
                a[r][0] = fma2(s, w.x, a[r][0]);
                a[r][1] = fma2(s, w.y, a[r][1]);
            }
        }
    }
    __syncwarp();
}

__device__ __forceinline__ void initacc(const float* __restrict__ b, int ooff,
                                        u64 (&a)[4][2]) {
    const ulonglong2 bb = *reinterpret_cast<const ulonglong2*>(b + ooff);
#pragma unroll
    for (int r = 0; r < 4; ++r) { a[r][0] = bb.x; a[r][1] = bb.y; }
}

// f = tanh(y @ W1^T + b1) @ W2^T + b2 for 4 rows (this thread's 4-j slice).
__device__ __forceinline__ void rhs4(const SW* __restrict__ s, int ooff,
                                     float* __restrict__ pb,
                                     const float (&y)[4][4], float (&f)[4][4]) {
    u64 acc[4][2];
    initacc(s->b1, ooff, acc);
    mv4o(s->T1, ooff, pb, y, acc);
    float z[4][4];
#pragma unroll
    for (int r = 0; r < 4; ++r)
#pragma unroll
        for (int p = 0; p < 2; ++p) {
            const float2 v = unpack2(acc[r][p]);
            z[r][2 * p]     = tanhf_fast(v.x);
            z[r][2 * p + 1] = tanhf_fast(v.y);
        }
    initacc(s->b2, ooff, acc);
    mv4o(s->T2, ooff, pb, z, acc);
#pragma unroll
    for (int r = 0; r < 4; ++r)
#pragma unroll
        for (int p = 0; p < 2; ++p) {
            const float2 v = unpack2(acc[r][p]);
            f[r][2 * p] = v.x; f[r][2 * p + 1] = v.y;
        }
}

__device__ __forceinline__ void rk4(const SW* __restrict__ s, int ooff,
                                    float* __restrict__ pb,
                                    float (&h)[4][4], float span) {
    const float dt = span * (1.0f / NSTEPS);
#pragma unroll 1
    for (int st = 0; st < NSTEPS; ++st) {
        float yt[4][4], ks[4][4], kc[4][4];
#pragma unroll
        for (int r = 0; r < 4; ++r)
#pragma unroll
            for (int j = 0; j < 4; ++j) { yt[r][j] = h[r][j]; ks[r][j] = 0.0f; }
#pragma unroll 1
        for (int sg = 0; sg < 4; ++sg) {
            rhs4(s, ooff, pb, yt, kc);
            const float ws = (sg == 1 || sg == 2) ? 2.0f : 1.0f;
            const float cn = (sg < 2) ? 0.5f * dt : dt;
#pragma unroll
            for (int r = 0; r < 4; ++r)
#pragma unroll
                for (int j = 0; j < 4; ++j) {
                    ks[r][j] = fmaf(ws, kc[r][j], ks[r][j]);
                    yt[r][j] = fmaf(cn, kc[r][j], h[r][j]);  // extra at sg=3: harmless
                }
        }
#pragma unroll
        for (int r = 0; r < 4; ++r)
#pragma unroll
            for (int j = 0; j < 4; ++j)
                h[r][j] = fmaf(dt * (1.0f / 6.0f), ks[r][j], h[r][j]);
    }
}

// PyTorch-order GRU (r,z,n) on 4 rows, 4-j slice.
__device__ __forceinline__ void gru4(const SW* __restrict__ s, int ooff,
                                     float* __restrict__ pb,
                                     float (&h)[4][4], const float (&x)[4][4]) {
    u64 a1[4][2], a2[4][2];
    float rg[4][4], zg[4][4];
    // r gate
    initacc(s->br, ooff, a1);
    mv4o(s->Tih[0], ooff, pb, x, a1);
    mv4o(s->Thh[0], ooff, pb, h, a1);
#pragma unroll
    for (int r = 0; r < 4; ++r)
#pragma unroll
        for (int p = 0; p < 2; ++p) {
            const float2 v = unpack2(a1[r][p]);
            rg[r][2 * p]     = sigmoidf_fast(v.x);
            rg[r][2 * p + 1] = sigmoidf_fast(v.y);
        }
    // z gate
    initacc(s->bz, ooff, a1);
    mv4o(s->Tih[1], ooff, pb, x, a1);
    mv4o(s->Thh[1], ooff, pb, h, a1);
#pragma unroll
    for (int r = 0; r < 4; ++r)
#pragma unroll
        for (int p = 0; p < 2; ++p) {
            const float2 v = unpack2(a1[r][p]);
            zg[r][2 * p]     = sigmoidf_fast(v.x);
            zg[r][2 * p + 1] = sigmoidf_fast(v.y);
        }
    // n gate: input part (a1) and hidden part (a2)
    initacc(s->bni, ooff, a1);
    mv4o(s->Tih[2], ooff, pb, x, a1);
    initacc(s->bnh, ooff, a2);
    mv4o(s->Thh[2], ooff, pb, h, a2);
#pragma unroll
    for (int r = 0; r < 4; ++r)
#pragma unroll
        for (int p = 0; p < 2; ++p) {
            const float2 gi = unpack2(a1[r][p]);
            const float2 gh = unpack2(a2[r][p]);
            const float n0 = tanhf_fast(gi.x + rg[r][2 * p] * gh.x);
            const float n1 = tanhf_fast(gi.y + rg[r][2 * p + 1] * gh.y);
            h[r][2 * p]     = n0 + zg[r][2 * p]     * (h[r][2 * p]     - n0);
            h[r][2 * p + 1] = n1 + zg[r][2 * p + 1] * (h[r][2 * p + 1] - n1);
        }
}

__device__ __forceinline__ void load4(const float* __restrict__ p, float (&v)[4]) {
    const float4 a = *reinterpret_cast<const float4*>(p);
    v[0] = a.x; v[1] = a.y; v[2] = a.z; v[3] = a.w;
}

extern "C" __global__ void __launch_bounds__(128, 3)
ode_gru_kernel(const float* __restrict__ inputs, const float* __restrict__ h0,
               const float* __restrict__ Wih, const float* __restrict__ Whh,
               const float* __restrict__ bih, const float* __restrict__ bhh,
               const float* __restrict__ W1, const float* __restrict__ b1,
               const float* __restrict__ W2, const float* __restrict__ b2,
               float* __restrict__ out, int B) {
    __shared__ SW s;
    __shared__ float ybuf[16 * GRP_STRIDE];   // 16 oct-groups per 128-thread CTA

    for (int i = threadIdx.x; i < 1024; i += blockDim.x) {
        const int j = i >> 5, k = i & 31;
        s.T1[k * 32 + j] = W1[i];
        s.T2[k * 32 + j] = W2[i];
    }
    for (int i = threadIdx.x; i < 3072; i += blockDim.x) {
        const int g = i >> 10, r = (i >> 5) & 31, k = i & 31;
        s.Tih[g][k * 32 + r] = Wih[i];
        s.Thh[g][k * 32 + r] = Whh[i];
    }
    for (int i = threadIdx.x; i < 32; i += blockDim.x) {
        s.b1[i]  = b1[i];            s.b2[i]  = b2[i];
        s.br[i]  = bih[i] + bhh[i];  s.bz[i]  = bih[32 + i] + bhh[32 + i];
        s.bni[i] = bih[64 + i];      s.bnh[i] = bhh[64 + i];
    }
    __syncthreads();

    const int gt   = blockIdx.x * blockDim.x + threadIdx.x;
    const int grp4 = gt >> 3;            // 4-row group index (8 lanes each)
    const int ooff = (gt & 7) * 4;       // j-slice offset
    const int row0 = grp4 * 4;
    if (row0 >= B) return;               // grid sized exactly: never taken

    float* pb = ybuf + (threadIdx.x >> 3) * GRP_STRIDE;

    float h[4][4];
#pragma unroll
    for (int r = 0; r < 4; ++r) load4(h0 + (size_t)(row0 + r) * 32 + ooff, h[r]);

    const float* xb = inputs + (size_t)row0 * TT * 32 + ooff;

    // initial integration over [0, 1]
    rk4(&s, ooff, pb, h, 1.0f);

#pragma unroll 1
    for (int t = 0; t < TT; ++t) {
        float x[4][4];
#pragma unroll
        for (int r = 0; r < 4; ++r)
            load4(xb + (size_t)r * TT * 32 + t * 32, x[r]);
        gru4(&s, ooff, pb, h, x);
        if (t < TT - 1) rk4(&s, ooff, pb, h, 1.0f);
    }

    // h_start -> out[0], then 14-unit integration -> out[1]
#pragma unroll
    for (int r = 0; r < 4; ++r) {
        float4 o = make_float4(fmaxf(h[r][0], 0.0f), fmaxf(h[r][1], 0.0f),
                               fmaxf(h[r][2], 0.0f), fmaxf(h[r][3], 0.0f));
        *reinterpret_cast<float4*>(out + (size_t)(row0 + r) * 32 + ooff) = o;
    }
    rk4(&s, ooff, pb, h, 14.0f);
#pragma unroll
    for (int r = 0; r < 4; ++r) {
        float4 o = make_float4(fmaxf(h[r][0], 0.0f), fmaxf(h[r][1], 0.0f),
                               fmaxf(h[r][2], 0.0f), fmaxf(h[r][3], 0.0f));
        *reinterpret_cast<float4*>(out + (size_t)B * 32 + (size_t)(row0 + r) * 32 + ooff) = o;
    }
}

extern "C" void kernel_launch(void* const* d_in, const int* in_sizes, int n_in,
                              void* d_out, int out_size) {
    const float* inputs = (const float*)d_in[0];
    const float* h0     = (const float*)d_in[1];
    const float* Wih    = (const float*)d_in[2];
    const float* Whh    = (const float*)d_in[3];
    const float* bih    = (const float*)d_in[4];
    const float* bhh    = (const float*)d_in[5];
    const float* W1     = (const float*)d_in[6];
    const float* b1     = (const float*)d_in[7];
    const float* W2     = (const float*)d_in[8];
    const float* b2     = (const float*)d_in[9];

    const int B = in_sizes[1] / 32;          // h0 is [B, 32]
    const int threads = 128;
    const long total = ((long)B / 4) * 8;    // 8 threads per 4-row group
    const int blocks = (int)((total + threads - 1) / threads);
    ode_gru_kernel<<<blocks, threads>>>(inputs, h0, Wih, Whh, bih, bhh,
                                        W1, b1, W2, b2, (float*)d_out, B);
}